// round 14
// baseline (speedup 1.0000x reference)
#include <cuda_runtime.h>
#include <cstdint>

#define NMAX 100000
#define EMAX 3300000
#define MMAX 8192
#define KINF 0xFFFFFFFFFFFFFFFFULL
#define MAXB 1024

// ---------------- static device scratch (no allocations allowed) -------------
__device__ unsigned long long g_key[NMAX];
__device__ unsigned long long g_minCur[NMAX];
__device__ unsigned long long g_minNew[NMAX];
__device__ unsigned char g_mask[NMAX];
__device__ unsigned char g_maskP[NMAX];
__device__ unsigned char g_mis[NMAX];
__device__ int g_misIdx[NMAX];
__device__ int g_cluster[NMAX];
__device__ unsigned int g_dense[(size_t)MMAX * (size_t)MMAX];  // u32 fixed-point, 0 = absent
__device__ int g_nodeCnt[MAXB];
__device__ int g_nodeOff[MAXB];
__device__ int g_cellCnt[MAXB];
__device__ int g_cellOff[MAXB];
__device__ int g_cnt2[2];
__device__ unsigned long long g_maxMisKey;
__device__ int g_M;
__device__ int g_P;
__device__ unsigned int g_arrive;

// ---------------- helpers ----------------------------------------------------

__device__ __forceinline__ void grid_bar(unsigned nb, unsigned &target) {
    __threadfence();
    __syncthreads();
    if (threadIdx.x == 0) {
        target += nb;
        atomicAdd(&g_arrive, 1u);
        while (*((volatile unsigned*)&g_arrive) < target) __nanosleep(64);
        __threadfence();
    }
    __syncthreads();
}

__device__ __forceinline__ int block_reduce_add(int v) {
    __shared__ int shr[32];
    int lane = threadIdx.x & 31;
    int w = threadIdx.x >> 5;
    #pragma unroll
    for (int o = 16; o; o >>= 1) v += __shfl_down_sync(0xffffffffu, v, o);
    if (lane == 0) shr[w] = v;
    __syncthreads();
    int nw = (blockDim.x + 31) >> 5;
    int r = 0;
    if (w == 0) {
        r = (lane < nw) ? shr[lane] : 0;
        #pragma unroll
        for (int o = 16; o; o >>= 1) r += __shfl_down_sync(0xffffffffu, r, o);
    }
    __syncthreads();
    return r;  // valid on threadIdx.x == 0
}

__device__ __forceinline__ int block_excl_scan(int v, int &total) {
    __shared__ int sh[1024];
    int t = threadIdx.x;
    sh[t] = v;
    __syncthreads();
    for (int off = 1; off < blockDim.x; off <<= 1) {
        int y = (t >= off) ? sh[t - off] : 0;
        __syncthreads();
        sh[t] += y;
        __syncthreads();
    }
    int incl = sh[t];
    total = sh[blockDim.x - 1];
    __syncthreads();
    return incl - v;
}

// read-filtered atomicMin: stale read >= actual, so skipping when mv >= cur is safe.
__device__ __forceinline__ void propF(int row, int col) {
    unsigned long long mv = g_minCur[row];
    if (mv != KINF) {
        unsigned long long c = g_minNew[col];
        if (mv < c) atomicMin(&g_minNew[col], mv);
    }
}
__device__ __forceinline__ void dil(int row, int col) {
    if (g_mask[row]) g_maskP[col] = 1;
}

// ---------------- kernels -----------------------------------------------------

__global__ void k_init(const float* __restrict__ score, int n) {
    int v = blockIdx.x * blockDim.x + threadIdx.x;
    if (v < n) {
        unsigned long long k =
            ((unsigned long long)__float_as_uint(score[v]) << 32) | (unsigned)v;
        g_key[v] = k; g_minCur[v] = k; g_minNew[v] = k;
        g_mask[v] = 0; g_maskP[v] = 0; g_mis[v] = 0;
    }
    if (v == 0) {
        g_arrive = 0;
        g_cnt2[0] = 0; g_cnt2[1] = 1;   // slot 1 read at top of round 0
        g_maxMisKey = 0; g_M = 0; g_P = 0;
    }
}

// Persistent kernel: full MIS loop + clustering (R1-proven, frozen).
__global__ void __launch_bounds__(256, 4)
k_persist(const int* __restrict__ erow, const int* __restrict__ ecol,
          int n, int e, const float* __restrict__ x, int d,
          float* __restrict__ out)
{
    const unsigned nb = gridDim.x;
    const unsigned nt = nb * blockDim.x;
    const unsigned tid = blockIdx.x * blockDim.x + threadIdx.x;
    unsigned bt = 0;
    const bool vecok = ((e & 3) == 0);
    const unsigned e4 = (unsigned)e >> 2;

    for (int round = 0; round < 100000; ++round) {
        if (*((volatile int*)&g_cnt2[(round + 1) & 1]) == 0) break;

        // A: min-key propagation
        if (vecok) {
            for (unsigned i = tid; i < e4; i += nt) {
                int4 r = __ldg((const int4*)erow + i);
                int4 c = __ldg((const int4*)ecol + i);
                propF(r.x, c.x); propF(r.y, c.y);
                propF(r.z, c.z); propF(r.w, c.w);
            }
        } else {
            for (unsigned i = tid; i < (unsigned)e; i += nt)
                propF(erow[i], ecol[i]);
        }
        grid_bar(nb, bt);

        // B: local minima join MIS
        if (tid == 0) g_cnt2[(round + 1) & 1] = 0;
        for (unsigned v = tid; v < (unsigned)n; v += nt) {
            unsigned char m = g_mask[v];
            if (!m && g_key[v] == g_minNew[v]) { g_mis[v] = 1; g_mask[v] = 1; m = 1; }
            g_maskP[v] = m;
        }
        grid_bar(nb, bt);

        // C: mask dilation by exactly 1 hop
        if (vecok) {
            for (unsigned i = tid; i < e4; i += nt) {
                int4 r = __ldg((const int4*)erow + i);
                int4 c = __ldg((const int4*)ecol + i);
                dil(r.x, c.x); dil(r.y, c.y); dil(r.z, c.z); dil(r.w, c.w);
            }
        } else {
            for (unsigned i = tid; i < (unsigned)e; i += nt)
                dil(erow[i], ecol[i]);
        }
        grid_bar(nb, bt);

        // D: commit mask, reset min arrays, count unmasked
        int local = 0;
        for (unsigned v = tid; v < (unsigned)n; v += nt) {
            unsigned char m = g_maskP[v];
            g_mask[v] = m;
            unsigned long long val = m ? KINF : g_key[v];
            g_minCur[v] = val; g_minNew[v] = val;
            local += (m == 0);
        }
        int bs = block_reduce_add(local);
        if (threadIdx.x == 0 && bs) atomicAdd(&g_cnt2[round & 1], bs);
        grid_bar(nb, bt);
    }

    // ---------------- clustering ---------------------------------------------
    for (unsigned v = tid; v < (unsigned)n; v += nt) {
        unsigned long long mc;
        if (g_mis[v]) { mc = g_key[v]; atomicMax(&g_maxMisKey, mc); }
        else mc = KINF;
        g_minCur[v] = mc; g_minNew[v] = mc;
    }
    int chunk = (n + (int)nb - 1) / (int)nb;
    int cs = (int)blockIdx.x * chunk;
    int ce = cs + chunk; if (ce > n) ce = n;
    {
        int cnt = 0;
        for (int v = cs + (int)threadIdx.x; v < ce; v += (int)blockDim.x)
            cnt += g_mis[v];
        int bs = block_reduce_add(cnt);
        if (threadIdx.x == 0) g_nodeCnt[blockIdx.x] = bs;
    }
    grid_bar(nb, bt);

    if (blockIdx.x == 0 && threadIdx.x == 0) {
        int s = 0;
        for (unsigned i = 0; i < nb; ++i) { int c = g_nodeCnt[i]; g_nodeOff[i] = s; s += c; }
        if (s > MMAX) s = MMAX;
        g_M = s;
    }
    grid_bar(nb, bt);

    {
        int run = g_nodeOff[blockIdx.x];
        for (int t0 = cs; t0 < ce; t0 += (int)blockDim.x) {
            int v = t0 + (int)threadIdx.x;
            int f = (v < ce) ? (int)g_mis[v] : 0;
            int tot;
            int ex = block_excl_scan(f, tot);
            if (v < ce) g_misIdx[v] = run + ex;
            run += tot;
        }
    }
    grid_bar(nb, bt);

    // H: one min-key propagation (k = 1), full edge list
    if (vecok) {
        for (unsigned i = tid; i < e4; i += nt) {
            int4 r = __ldg((const int4*)erow + i);
            int4 c = __ldg((const int4*)ecol + i);
            propF(r.x, c.x); propF(r.y, c.y); propF(r.z, c.z); propF(r.w, c.w);
        }
    } else {
        for (unsigned i = tid; i < (unsigned)e; i += nt)
            propF(erow[i], ecol[i]);
    }
    grid_bar(nb, bt);

    // I: cluster assignment
    int fb = g_misIdx[(unsigned)(g_maxMisKey & 0xffffffffULL)];
    for (unsigned v = tid; v < (unsigned)n; v += nt) {
        unsigned long long mk = g_minNew[v];
        g_cluster[v] = (mk == KINF) ? fb : g_misIdx[(unsigned)(mk & 0xffffffffULL)];
    }

    // J: x_out = x[mis]
    if ((d & 3) == 0) {
        int dv = d >> 2;
        for (unsigned v = tid; v < (unsigned)n; v += nt) {
            if (g_mis[v]) {
                const float4* src = (const float4*)(x + (size_t)v * d);
                float4* dst = (float4*)(out + (size_t)g_misIdx[v] * d);
                for (int j = 0; j < dv; ++j) dst[j] = src[j];
            }
        }
    } else {
        for (unsigned v = tid; v < (unsigned)n; v += nt) {
            if (g_mis[v]) {
                const float* src = x + (size_t)v * d;
                float* dst = out + (size_t)g_misIdx[v] * d;
                for (int j = 0; j < d; ++j) dst[j] = src[j];
            }
        }
    }
}

// ---------------- dense pipeline (u32 fixed-point, R12-proven) -----------------
// inc = round(attr*2^16) + 1: +1 guarantees presence (acc != 0).
// IMPORTANT: atomicAdd return value is UNUSED -> compiles to RED (0.854 cyc/lane),
// not ATOM (318-cyc round trip). R13 regression came from consuming the return.

__global__ void k_accum(const int* __restrict__ erow, const int* __restrict__ ecol,
                        const float* __restrict__ attr, int e) {
    unsigned M = (unsigned)g_M;
    unsigned nt = gridDim.x * blockDim.x;
    unsigned t = blockIdx.x * blockDim.x + threadIdx.x;
    const float SC = 65536.0f;
    if ((e & 3) == 0) {
        unsigned e4 = (unsigned)e >> 2;
        for (unsigned i = t; i < e4; i += nt) {
            int4 r = __ldg((const int4*)erow + i);
            int4 c = __ldg((const int4*)ecol + i);
            float4 a = __ldg((const float4*)attr + i);
            unsigned i0 = (unsigned)g_cluster[r.x] * M + (unsigned)g_cluster[c.x];
            unsigned i1 = (unsigned)g_cluster[r.y] * M + (unsigned)g_cluster[c.y];
            unsigned i2 = (unsigned)g_cluster[r.z] * M + (unsigned)g_cluster[c.z];
            unsigned i3 = (unsigned)g_cluster[r.w] * M + (unsigned)g_cluster[c.w];
            atomicAdd(&g_dense[i0], __float2uint_rn(a.x * SC) + 1u);
            atomicAdd(&g_dense[i1], __float2uint_rn(a.y * SC) + 1u);
            atomicAdd(&g_dense[i2], __float2uint_rn(a.z * SC) + 1u);
            atomicAdd(&g_dense[i3], __float2uint_rn(a.w * SC) + 1u);
        }
    } else {
        for (unsigned i = t; i < (unsigned)e; i += nt) {
            unsigned idx = (unsigned)g_cluster[erow[i]] * M + (unsigned)g_cluster[ecol[i]];
            atomicAdd(&g_dense[idx], __float2uint_rn(attr[i] * SC) + 1u);
        }
    }
}

__global__ void k_count() {
    unsigned M = (unsigned)g_M;
    size_t MM = (size_t)M * M;
    size_t chunk = (MM + gridDim.x - 1) / gridDim.x;
    size_t s = (size_t)blockIdx.x * chunk;
    size_t epos = s + chunk; if (epos > MM) epos = MM;
    int cnt = 0;
    for (size_t i = s + threadIdx.x; i < epos; i += blockDim.x) {
        if (g_dense[i] != 0u) {
            unsigned ii = (unsigned)i;
            unsigned r = ii / M, c = ii - r * M;
            cnt += (r != c);
        }
    }
    int bs = block_reduce_add(cnt);
    if (threadIdx.x == 0) g_cellCnt[blockIdx.x] = bs;
}

__global__ void k_scan(int nb2) {
    int t = threadIdx.x;
    int v = (t < nb2) ? g_cellCnt[t] : 0;
    int tot;
    int ex = block_excl_scan(v, tot);
    if (t < nb2) g_cellOff[t] = ex;
    if (t == 0) g_P = tot;
}

__global__ void k_write(float* __restrict__ out, int d) {
    unsigned M = (unsigned)g_M;
    size_t MM = (size_t)M * M;
    size_t P = (size_t)g_P;
    size_t xoff = (size_t)M * (size_t)d;
    size_t chunk = (MM + gridDim.x - 1) / gridDim.x;
    size_t s = (size_t)blockIdx.x * chunk;
    size_t epos = s + chunk; if (epos > MM) epos = MM;
    size_t base = (size_t)g_cellOff[blockIdx.x];
    const float INV = 1.0f / 65536.0f;
    for (size_t t0 = s; t0 < epos; t0 += blockDim.x) {
        size_t i = t0 + threadIdx.x;
        int keep = 0; unsigned r = 0, c = 0; float val = 0.f;
        if (i < epos) {
            unsigned a = g_dense[i];
            if (a != 0u) {
                unsigned ii = (unsigned)i;
                r = ii / M; c = ii - r * M;
                if (r != c) { keep = 1; val = (float)a * INV; }
            }
        }
        int tot;
        int ex = block_excl_scan(keep, tot);
        if (keep) {
            size_t p = base + (size_t)ex;
            out[xoff + p] = (float)r;
            out[xoff + P + p] = (float)c;
            out[xoff + 2 * P + p] = val;
        }
        base += tot;
    }
}

__global__ void k_tail(float* __restrict__ out, const float* __restrict__ score,
                       int n, int d) {
    int v = blockIdx.x * blockDim.x + threadIdx.x;
    if (v >= n) return;
    size_t off = (size_t)g_M * (size_t)d + 3 * (size_t)g_P;
    out[off + v] = (float)g_cluster[v];
    out[off + (size_t)n + v] = g_mis[v] ? 1.0f : 0.0f;
    out[off + 2 * (size_t)n + v] = score[v];
}

// ---------------- entry -------------------------------------------------------

static cudaStream_t s_side = nullptr;
static cudaEvent_t s_evFork = nullptr;
static cudaEvent_t s_evJoin = nullptr;
static void* s_densePtr = nullptr;

extern "C" void kernel_launch(void* const* d_in, const int* in_sizes, int n_in,
                              void* d_out, int out_size) {
    const float* x = (const float*)d_in[0];
    const int* ei = (const int*)d_in[1];
    const float* attr = (const float*)d_in[2];
    const float* score = (const float*)d_in[3];
    int n = in_sizes[3];
    int e = in_sizes[1] / 2;
    int d = in_sizes[0] / n;
    const int* erow = ei;
    const int* ecol = ei + e;
    float* out = (float*)d_out;

    // one-time resources (created on the uncaptured correctness call)
    if (!s_side) {
        cudaStreamCreateWithFlags(&s_side, cudaStreamNonBlocking);
        cudaEventCreateWithFlags(&s_evFork, cudaEventDisableTiming);
        cudaEventCreateWithFlags(&s_evJoin, cudaEventDisableTiming);
        cudaGetSymbolAddress(&s_densePtr, g_dense);
    }

    int dev = 0;
    cudaGetDevice(&dev);
    int sms = 148;
    cudaDeviceGetAttribute(&sms, cudaDevAttrMultiProcessorCount, dev);
    int nb = sms * 4;
    if (nb > MAXB) nb = MAXB;

    k_init<<<(n + 255) / 256, 256>>>(score, n);

    // fork: zero dense on side stream, overlapped with the persistent kernel
    cudaEventRecord(s_evFork, 0);
    cudaStreamWaitEvent(s_side, s_evFork, 0);
    cudaMemsetAsync(s_densePtr, 0, (size_t)MMAX * (size_t)MMAX * 4, s_side);

    k_persist<<<nb, 256>>>(erow, ecol, n, e, x, d, out);

    // join: accum needs both persist (stream order) and the memset (event)
    cudaEventRecord(s_evJoin, s_side);
    cudaStreamWaitEvent(0, s_evJoin, 0);

    k_accum<<<4096, 256>>>(erow, ecol, attr, e);
    k_count<<<MAXB, 256>>>();
    k_scan<<<1, 1024>>>(MAXB);
    k_write<<<MAXB, 256>>>(out, d);
    k_tail<<<(n + 255) / 256, 256>>>(out, score, n, d);
}

// round 15
// speedup vs baseline: 1.1959x; 1.1959x over previous
#include <cuda_runtime.h>
#include <cstdint>

#define NMAX 100000
#define EMAX 3300000
#define MMAX 8192
#define KINF 0xFFFFFFFFFFFFFFFFULL
#define MAXB 1024

// ---------------- static device scratch (no allocations allowed) -------------
__device__ unsigned long long g_key[NMAX];
__device__ unsigned long long g_minCur[NMAX];
__device__ unsigned long long g_minNew[NMAX];
__device__ unsigned char g_mask[NMAX];
__device__ unsigned char g_maskP[NMAX];
__device__ unsigned char g_mis[NMAX];
__device__ int g_misIdx[NMAX];
__device__ int g_cluster[NMAX];
__device__ unsigned int g_dense[(size_t)MMAX * (size_t)MMAX];  // u32 fixed-point, 0 = absent
__device__ int g_nodeCnt[MAXB];
__device__ int g_nodeOff[MAXB];
__device__ int g_cellCnt[MAXB];
__device__ int g_cellOff[MAXB];
__device__ int g_cnt2[2];
__device__ unsigned long long g_maxMisKey;
__device__ int g_M;
__device__ int g_P;
__device__ unsigned int g_arrive;

// ---------------- helpers ----------------------------------------------------

__device__ __forceinline__ void grid_bar(unsigned nb, unsigned &target) {
    __threadfence();
    __syncthreads();
    if (threadIdx.x == 0) {
        target += nb;
        atomicAdd(&g_arrive, 1u);
        while (*((volatile unsigned*)&g_arrive) < target) __nanosleep(64);
        __threadfence();
    }
    __syncthreads();
}

__device__ __forceinline__ int block_reduce_add(int v) {
    __shared__ int shr[32];
    int lane = threadIdx.x & 31;
    int w = threadIdx.x >> 5;
    #pragma unroll
    for (int o = 16; o; o >>= 1) v += __shfl_down_sync(0xffffffffu, v, o);
    if (lane == 0) shr[w] = v;
    __syncthreads();
    int nw = (blockDim.x + 31) >> 5;
    int r = 0;
    if (w == 0) {
        r = (lane < nw) ? shr[lane] : 0;
        #pragma unroll
        for (int o = 16; o; o >>= 1) r += __shfl_down_sync(0xffffffffu, r, o);
    }
    __syncthreads();
    return r;  // valid on threadIdx.x == 0
}

__device__ __forceinline__ int block_excl_scan(int v, int &total) {
    __shared__ int sh[1024];
    int t = threadIdx.x;
    sh[t] = v;
    __syncthreads();
    for (int off = 1; off < blockDim.x; off <<= 1) {
        int y = (t >= off) ? sh[t - off] : 0;
        __syncthreads();
        sh[t] += y;
        __syncthreads();
    }
    int incl = sh[t];
    total = sh[blockDim.x - 1];
    __syncthreads();
    return incl - v;
}

// read-filtered atomicMin: stale read >= actual, so skipping when mv >= cur is safe.
__device__ __forceinline__ void propF(int row, int col) {
    unsigned long long mv = g_minCur[row];
    if (mv != KINF) {
        unsigned long long c = g_minNew[col];
        if (mv < c) atomicMin(&g_minNew[col], mv);
    }
}
__device__ __forceinline__ void dil(int row, int col) {
    if (g_mask[row]) g_maskP[col] = 1;
}

// ---------------- kernels -----------------------------------------------------

__global__ void k_init(const float* __restrict__ score, int n) {
    int v = blockIdx.x * blockDim.x + threadIdx.x;
    if (v < n) {
        unsigned long long k =
            ((unsigned long long)__float_as_uint(score[v]) << 32) | (unsigned)v;
        g_key[v] = k; g_minCur[v] = k; g_minNew[v] = k;
        g_mask[v] = 0; g_maskP[v] = 0; g_mis[v] = 0;
    }
    if (v == 0) {
        g_arrive = 0;
        g_cnt2[0] = 0; g_cnt2[1] = 1;   // slot 1 read at top of round 0
        g_maxMisKey = 0; g_M = 0; g_P = 0;
    }
}

// Persistent kernel: full MIS loop + clustering (R1-proven, frozen).
__global__ void __launch_bounds__(256, 4)
k_persist(const int* __restrict__ erow, const int* __restrict__ ecol,
          int n, int e, const float* __restrict__ x, int d,
          float* __restrict__ out)
{
    const unsigned nb = gridDim.x;
    const unsigned nt = nb * blockDim.x;
    const unsigned tid = blockIdx.x * blockDim.x + threadIdx.x;
    unsigned bt = 0;
    const bool vecok = ((e & 3) == 0);
    const unsigned e4 = (unsigned)e >> 2;

    for (int round = 0; round < 100000; ++round) {
        if (*((volatile int*)&g_cnt2[(round + 1) & 1]) == 0) break;

        // A: min-key propagation
        if (vecok) {
            for (unsigned i = tid; i < e4; i += nt) {
                int4 r = __ldg((const int4*)erow + i);
                int4 c = __ldg((const int4*)ecol + i);
                propF(r.x, c.x); propF(r.y, c.y);
                propF(r.z, c.z); propF(r.w, c.w);
            }
        } else {
            for (unsigned i = tid; i < (unsigned)e; i += nt)
                propF(erow[i], ecol[i]);
        }
        grid_bar(nb, bt);

        // B: local minima join MIS
        if (tid == 0) g_cnt2[(round + 1) & 1] = 0;
        for (unsigned v = tid; v < (unsigned)n; v += nt) {
            unsigned char m = g_mask[v];
            if (!m && g_key[v] == g_minNew[v]) { g_mis[v] = 1; g_mask[v] = 1; m = 1; }
            g_maskP[v] = m;
        }
        grid_bar(nb, bt);

        // C: mask dilation by exactly 1 hop
        if (vecok) {
            for (unsigned i = tid; i < e4; i += nt) {
                int4 r = __ldg((const int4*)erow + i);
                int4 c = __ldg((const int4*)ecol + i);
                dil(r.x, c.x); dil(r.y, c.y); dil(r.z, c.z); dil(r.w, c.w);
            }
        } else {
            for (unsigned i = tid; i < (unsigned)e; i += nt)
                dil(erow[i], ecol[i]);
        }
        grid_bar(nb, bt);

        // D: commit mask, reset min arrays, count unmasked
        int local = 0;
        for (unsigned v = tid; v < (unsigned)n; v += nt) {
            unsigned char m = g_maskP[v];
            g_mask[v] = m;
            unsigned long long val = m ? KINF : g_key[v];
            g_minCur[v] = val; g_minNew[v] = val;
            local += (m == 0);
        }
        int bs = block_reduce_add(local);
        if (threadIdx.x == 0 && bs) atomicAdd(&g_cnt2[round & 1], bs);
        grid_bar(nb, bt);
    }

    // ---------------- clustering ---------------------------------------------
    for (unsigned v = tid; v < (unsigned)n; v += nt) {
        unsigned long long mc;
        if (g_mis[v]) { mc = g_key[v]; atomicMax(&g_maxMisKey, mc); }
        else mc = KINF;
        g_minCur[v] = mc; g_minNew[v] = mc;
    }
    int chunk = (n + (int)nb - 1) / (int)nb;
    int cs = (int)blockIdx.x * chunk;
    int ce = cs + chunk; if (ce > n) ce = n;
    {
        int cnt = 0;
        for (int v = cs + (int)threadIdx.x; v < ce; v += (int)blockDim.x)
            cnt += g_mis[v];
        int bs = block_reduce_add(cnt);
        if (threadIdx.x == 0) g_nodeCnt[blockIdx.x] = bs;
    }
    grid_bar(nb, bt);

    if (blockIdx.x == 0 && threadIdx.x == 0) {
        int s = 0;
        for (unsigned i = 0; i < nb; ++i) { int c = g_nodeCnt[i]; g_nodeOff[i] = s; s += c; }
        if (s > MMAX) s = MMAX;
        g_M = s;
    }
    grid_bar(nb, bt);

    {
        int run = g_nodeOff[blockIdx.x];
        for (int t0 = cs; t0 < ce; t0 += (int)blockDim.x) {
            int v = t0 + (int)threadIdx.x;
            int f = (v < ce) ? (int)g_mis[v] : 0;
            int tot;
            int ex = block_excl_scan(f, tot);
            if (v < ce) g_misIdx[v] = run + ex;
            run += tot;
        }
    }
    grid_bar(nb, bt);

    // H: one min-key propagation (k = 1), full edge list
    if (vecok) {
        for (unsigned i = tid; i < e4; i += nt) {
            int4 r = __ldg((const int4*)erow + i);
            int4 c = __ldg((const int4*)ecol + i);
            propF(r.x, c.x); propF(r.y, c.y); propF(r.z, c.z); propF(r.w, c.w);
        }
    } else {
        for (unsigned i = tid; i < (unsigned)e; i += nt)
            propF(erow[i], ecol[i]);
    }
    grid_bar(nb, bt);

    // I: cluster assignment
    int fb = g_misIdx[(unsigned)(g_maxMisKey & 0xffffffffULL)];
    for (unsigned v = tid; v < (unsigned)n; v += nt) {
        unsigned long long mk = g_minNew[v];
        g_cluster[v] = (mk == KINF) ? fb : g_misIdx[(unsigned)(mk & 0xffffffffULL)];
    }

    // J: x_out = x[mis]
    if ((d & 3) == 0) {
        int dv = d >> 2;
        for (unsigned v = tid; v < (unsigned)n; v += nt) {
            if (g_mis[v]) {
                const float4* src = (const float4*)(x + (size_t)v * d);
                float4* dst = (float4*)(out + (size_t)g_misIdx[v] * d);
                for (int j = 0; j < dv; ++j) dst[j] = src[j];
            }
        }
    } else {
        for (unsigned v = tid; v < (unsigned)n; v += nt) {
            if (g_mis[v]) {
                const float* src = x + (size_t)v * d;
                float* dst = out + (size_t)g_misIdx[v] * d;
                for (int j = 0; j < d; ++j) dst[j] = src[j];
            }
        }
    }
}

// ---------------- dense pipeline (u32 fixed-point, R12-proven core) ------------
// inc = round(attr*2^16) + 1: +1 guarantees presence (acc != 0).
// atomicAdd return value UNUSED -> RED (fast path), per R13's lesson.
// Chunk decomposition is shared by k_count and k_write (multiple of 4 cells).

__global__ void k_zero() {
    size_t MM = (size_t)g_M * (size_t)g_M;
    size_t nt = (size_t)gridDim.x * blockDim.x;
    for (size_t i = (size_t)blockIdx.x * blockDim.x + threadIdx.x; i < MM; i += nt)
        g_dense[i] = 0u;
}

__global__ void k_accum(const int* __restrict__ erow, const int* __restrict__ ecol,
                        const float* __restrict__ attr, int e) {
    unsigned M = (unsigned)g_M;
    unsigned nt = gridDim.x * blockDim.x;
    unsigned t = blockIdx.x * blockDim.x + threadIdx.x;
    const float SC = 65536.0f;
    if ((e & 3) == 0) {
        unsigned e4 = (unsigned)e >> 2;
        for (unsigned i = t; i < e4; i += nt) {
            int4 r = __ldg((const int4*)erow + i);
            int4 c = __ldg((const int4*)ecol + i);
            float4 a = __ldg((const float4*)attr + i);
            unsigned i0 = (unsigned)g_cluster[r.x] * M + (unsigned)g_cluster[c.x];
            unsigned i1 = (unsigned)g_cluster[r.y] * M + (unsigned)g_cluster[c.y];
            unsigned i2 = (unsigned)g_cluster[r.z] * M + (unsigned)g_cluster[c.z];
            unsigned i3 = (unsigned)g_cluster[r.w] * M + (unsigned)g_cluster[c.w];
            atomicAdd(&g_dense[i0], __float2uint_rn(a.x * SC) + 1u);
            atomicAdd(&g_dense[i1], __float2uint_rn(a.y * SC) + 1u);
            atomicAdd(&g_dense[i2], __float2uint_rn(a.z * SC) + 1u);
            atomicAdd(&g_dense[i3], __float2uint_rn(a.w * SC) + 1u);
        }
    } else {
        for (unsigned i = t; i < (unsigned)e; i += nt) {
            unsigned idx = (unsigned)g_cluster[erow[i]] * M + (unsigned)g_cluster[ecol[i]];
            atomicAdd(&g_dense[idx], __float2uint_rn(attr[i] * SC) + 1u);
        }
    }
}

// k_count: uint4-vectorized presence count (chunk = multiple of 4, matches k_write).
__global__ void k_count() {
    unsigned M = (unsigned)g_M;
    size_t MM = (size_t)M * M;
    size_t chunk = (((MM + gridDim.x - 1) / gridDim.x) + 3) & ~(size_t)3;
    size_t s = (size_t)blockIdx.x * chunk;
    int cnt = 0;
    if (s < MM) {
        size_t epos = s + chunk; if (epos > MM) epos = MM;
        size_t n4 = (epos - s) >> 2;
        const uint4* p4 = (const uint4*)(g_dense + s);
        for (size_t j = threadIdx.x; j < n4; j += blockDim.x) {
            uint4 v = p4[j];
            unsigned i0 = (unsigned)(s + (j << 2));
            if (v.x) { unsigned r = i0 / M;       cnt += (i0       - r * M) != r; }
            if (v.y) { unsigned r = (i0+1) / M;   cnt += ((i0+1)   - r * M) != r; }
            if (v.z) { unsigned r = (i0+2) / M;   cnt += ((i0+2)   - r * M) != r; }
            if (v.w) { unsigned r = (i0+3) / M;   cnt += ((i0+3)   - r * M) != r; }
        }
        for (size_t i = s + (n4 << 2) + threadIdx.x; i < epos; i += blockDim.x) {
            if (g_dense[i]) {
                unsigned ii = (unsigned)i;
                unsigned r = ii / M;
                cnt += ((ii - r * M) != r);
            }
        }
    }
    int bs = block_reduce_add(cnt);
    if (threadIdx.x == 0) g_cellCnt[blockIdx.x] = bs;
}

__global__ void k_scan(int nb2) {
    int t = threadIdx.x;
    int v = (t < nb2) ? g_cellCnt[t] : 0;
    int tot;
    int ex = block_excl_scan(v, tot);
    if (t < nb2) g_cellOff[t] = ex;
    if (t == 0) g_P = tot;
}

// k_write: ballot-based tile compaction (2 syncs/tile vs 16). Order preserved:
// lane order within warp (popc of lower lanes), warp order via shared prefix.
__global__ void k_write(float* __restrict__ out, int d) {
    __shared__ int wtot[8];
    unsigned M = (unsigned)g_M;
    size_t MM = (size_t)M * M;
    size_t P = (size_t)g_P;
    size_t xoff = (size_t)M * (size_t)d;
    size_t chunk = (((MM + gridDim.x - 1) / gridDim.x) + 3) & ~(size_t)3;
    size_t s = (size_t)blockIdx.x * chunk;
    if (s >= MM) return;
    size_t epos = s + chunk; if (epos > MM) epos = MM;
    size_t base = (size_t)g_cellOff[blockIdx.x];
    const float INV = 1.0f / 65536.0f;
    int lane = threadIdx.x & 31;
    int wid = threadIdx.x >> 5;
    unsigned lmask = (1u << lane) - 1u;

    for (size_t t0 = s; t0 < epos; t0 += blockDim.x) {
        size_t i = t0 + threadIdx.x;
        int keep = 0; unsigned r = 0, c = 0; float val = 0.f;
        if (i < epos) {
            unsigned a = g_dense[i];
            if (a != 0u) {
                unsigned ii = (unsigned)i;
                r = ii / M; c = ii - r * M;
                if (r != c) { keep = 1; val = (float)a * INV; }
            }
        }
        unsigned bal = __ballot_sync(0xffffffffu, keep);
        if (lane == 0) wtot[wid] = __popc(bal);
        __syncthreads();
        int pre = 0, tileTot = 0;
        #pragma unroll
        for (int w2 = 0; w2 < 8; ++w2) {
            int v2 = wtot[w2];
            pre += (w2 < wid) ? v2 : 0;
            tileTot += v2;
        }
        if (keep) {
            size_t p = base + (size_t)(pre + __popc(bal & lmask));
            out[xoff + p] = (float)r;
            out[xoff + P + p] = (float)c;
            out[xoff + 2 * P + p] = val;
        }
        base += (size_t)tileTot;
        __syncthreads();   // protect wtot before next tile
    }
}

__global__ void k_tail(float* __restrict__ out, const float* __restrict__ score,
                       int n, int d) {
    int v = blockIdx.x * blockDim.x + threadIdx.x;
    if (v >= n) return;
    size_t off = (size_t)g_M * (size_t)d + 3 * (size_t)g_P;
    out[off + v] = (float)g_cluster[v];
    out[off + (size_t)n + v] = g_mis[v] ? 1.0f : 0.0f;
    out[off + 2 * (size_t)n + v] = score[v];
}

// ---------------- entry -------------------------------------------------------
extern "C" void kernel_launch(void* const* d_in, const int* in_sizes, int n_in,
                              void* d_out, int out_size) {
    const float* x = (const float*)d_in[0];
    const int* ei = (const int*)d_in[1];
    const float* attr = (const float*)d_in[2];
    const float* score = (const float*)d_in[3];
    int n = in_sizes[3];
    int e = in_sizes[1] / 2;
    int d = in_sizes[0] / n;
    const int* erow = ei;
    const int* ecol = ei + e;
    float* out = (float*)d_out;

    int dev = 0;
    cudaGetDevice(&dev);
    int sms = 148;
    cudaDeviceGetAttribute(&sms, cudaDevAttrMultiProcessorCount, dev);
    int nb = sms * 4;
    if (nb > MAXB) nb = MAXB;

    k_init<<<(n + 255) / 256, 256>>>(score, n);
    k_persist<<<nb, 256>>>(erow, ecol, n, e, x, d, out);
    k_zero<<<2048, 256>>>();
    k_accum<<<4096, 256>>>(erow, ecol, attr, e);
    k_count<<<MAXB, 256>>>();
    k_scan<<<1, 1024>>>(MAXB);
    k_write<<<MAXB, 256>>>(out, d);
    k_tail<<<(n + 255) / 256, 256>>>(out, score, n, d);
}